// round 1
// baseline (speedup 1.0000x reference)
#include <cuda_runtime.h>
#include <cuda_bf16.h>
#include <math.h>

// Problem constants
#define B_Q     1024
#define N_CAND  100000
#define D_NUM   64
#define D_CAT   32
#define D_IN    96
#define DIM     512
#define D_OUT   10
#define CHUNK   5000
#define NCHUNK  20

// Scratch (device globals; allocation-free)
__device__ float g_H[(size_t)N_CAND * DIM];    // candidate hidden
__device__ float g_C[(size_t)N_CAND * DIM];    // candidate encoding
__device__ float g_QH[(size_t)B_Q * DIM];      // query hidden
__device__ float g_Q[(size_t)B_Q * DIM];       // query encoding
__device__ float g_cnorm[N_CAND];
__device__ float g_qnorm[B_Q];
__device__ float g_logits[B_Q * D_OUT];
__device__ float g_chunks[B_Q * NCHUNK];

#define TS 128
#define KT 8

// ---------------------------------------------------------------------------
// Zero accumulators
// ---------------------------------------------------------------------------
__global__ void k_zero() {
    int i = blockIdx.x * blockDim.x + threadIdx.x;
    if (i < B_Q * D_OUT)  g_logits[i] = 0.f;
    if (i < B_Q * NCHUNK) g_chunks[i] = 0.f;
}

// ---------------------------------------------------------------------------
// Encoder GEMM: Out[M, 512] = act(A[M,K] @ W[K,512] + bias)
// CONCAT: A is the concat of A(num, ld=64) and A2(cat, ld=32), K=96.
// ---------------------------------------------------------------------------
template<bool CONCAT, bool RELU>
__global__ __launch_bounds__(256)
void k_gemm_enc(const float* __restrict__ A, const float* __restrict__ A2,
                const float* __restrict__ W, const float* __restrict__ bias,
                float* __restrict__ Out, int M, int K)
{
    __shared__ float As[KT][TS];
    __shared__ float Bs[KT][TS];
    const int tid = threadIdx.x;
    const int m0 = blockIdx.y * TS;
    const int n0 = blockIdx.x * TS;
    const int tx = tid & 15;
    const int ty = tid >> 4;

    float acc[8][8] = {};

    const int arow = tid >> 1;
    const int akp  = (tid & 1) * 4;
    const int bk   = tid >> 5;
    const int bn   = (tid & 31) * 4;

    for (int kt = 0; kt < K; kt += KT) {
        float4 av = make_float4(0.f, 0.f, 0.f, 0.f);
        const int gm = m0 + arow;
        const int gk = kt + akp;
        if (gm < M) {
            if (CONCAT) {
                if (gk < D_NUM) av = *(const float4*)(A  + (size_t)gm * D_NUM + gk);
                else            av = *(const float4*)(A2 + (size_t)gm * D_CAT + (gk - D_NUM));
            } else {
                av = *(const float4*)(A + (size_t)gm * K + gk);
            }
        }
        As[akp + 0][arow] = av.x;
        As[akp + 1][arow] = av.y;
        As[akp + 2][arow] = av.z;
        As[akp + 3][arow] = av.w;

        // W is [K, 512] row-major; 512 % 128 == 0, always in-bounds columns
        *(float4*)&Bs[bk][bn] = *(const float4*)(W + (size_t)(kt + bk) * DIM + n0 + bn);

        __syncthreads();
        #pragma unroll
        for (int kk = 0; kk < KT; kk++) {
            float a[8], b[8];
            #pragma unroll
            for (int i = 0; i < 4; i++) {
                a[i]     = As[kk][ty * 4 + i];
                a[4 + i] = As[kk][64 + ty * 4 + i];
                b[i]     = Bs[kk][tx * 4 + i];
                b[4 + i] = Bs[kk][64 + tx * 4 + i];
            }
            #pragma unroll
            for (int i = 0; i < 8; i++)
                #pragma unroll
                for (int j = 0; j < 8; j++)
                    acc[i][j] += a[i] * b[j];
        }
        __syncthreads();
    }

    #pragma unroll
    for (int i = 0; i < 8; i++) {
        const int ml = (i < 4) ? (ty * 4 + i) : (64 + ty * 4 + i - 4);
        const int gm = m0 + ml;
        if (gm >= M) continue;
        #pragma unroll
        for (int j = 0; j < 8; j++) {
            const int nl = (j < 4) ? (tx * 4 + j) : (64 + tx * 4 + j - 4);
            const int gn = n0 + nl;
            float v = acc[i][j] + bias[gn];
            if (RELU) v = fmaxf(v, 0.f);
            Out[(size_t)gm * DIM + gn] = v;
        }
    }
}

// ---------------------------------------------------------------------------
// Row squared-norms: out[row] = sum_k X[row][k]^2   (K = 512)
// ---------------------------------------------------------------------------
__global__ void k_norm(const float* __restrict__ X, float* __restrict__ out, int M)
{
    const int row = blockIdx.x * 8 + (threadIdx.x >> 5);
    const int lane = threadIdx.x & 31;
    if (row >= M) return;
    const float4* p = (const float4*)(X + (size_t)row * DIM);
    float s = 0.f;
    #pragma unroll
    for (int i = lane; i < DIM / 4; i += 32) {
        float4 v = p[i];
        s += v.x * v.x + v.y * v.y + v.z * v.z + v.w * v.w;
    }
    #pragma unroll
    for (int o = 16; o > 0; o >>= 1) s += __shfl_down_sync(0xffffffffu, s, o);
    if (lane == 0) out[row] = s;
}

// ---------------------------------------------------------------------------
// Distance GEMM + fused epilogue:
//   S = Q @ C^T  (K = 512)
//   ed = exp(-sqrt(max(qn + cn - 2S, 0)))
//   logits[b][cls[n]] += ed ;  chunks[b][n/5000] += exp(ed)
// ---------------------------------------------------------------------------
__global__ __launch_bounds__(256)
void k_dist(const float* __restrict__ Q, const float* __restrict__ C,
            const float* __restrict__ qn, const float* __restrict__ cn,
            const int* __restrict__ cy,
            float* __restrict__ logits, float* __restrict__ chunks, int N)
{
    __shared__ float As[KT][TS];
    __shared__ float Bs[KT][TS];
    __shared__ float lg[TS][D_OUT];
    __shared__ float ch[TS][2];

    const int tid = threadIdx.x;
    const int m0 = blockIdx.y * TS;
    const int n0 = blockIdx.x * TS;
    const int tx = tid & 15;
    const int ty = tid >> 4;

    for (int i = tid; i < TS * D_OUT; i += 256) ((float*)lg)[i] = 0.f;
    for (int i = tid; i < TS * 2; i += 256)     ((float*)ch)[i] = 0.f;

    float acc[8][8] = {};
    const int arow = tid >> 1;
    const int akp  = (tid & 1) * 4;

    __syncthreads();

    for (int kt = 0; kt < DIM; kt += KT) {
        // Q always full (M = 1024, grid.y = 8)
        float4 av = *(const float4*)(Q + (size_t)(m0 + arow) * DIM + kt + akp);
        const int gc = n0 + arow;
        float4 bv = make_float4(0.f, 0.f, 0.f, 0.f);
        if (gc < N) bv = *(const float4*)(C + (size_t)gc * DIM + kt + akp);

        As[akp + 0][arow] = av.x; As[akp + 1][arow] = av.y;
        As[akp + 2][arow] = av.z; As[akp + 3][arow] = av.w;
        Bs[akp + 0][arow] = bv.x; Bs[akp + 1][arow] = bv.y;
        Bs[akp + 2][arow] = bv.z; Bs[akp + 3][arow] = bv.w;

        __syncthreads();
        #pragma unroll
        for (int kk = 0; kk < KT; kk++) {
            float a[8], b[8];
            #pragma unroll
            for (int i = 0; i < 4; i++) {
                a[i]     = As[kk][ty * 4 + i];
                a[4 + i] = As[kk][64 + ty * 4 + i];
                b[i]     = Bs[kk][tx * 4 + i];
                b[4 + i] = Bs[kk][64 + tx * 4 + i];
            }
            #pragma unroll
            for (int i = 0; i < 8; i++)
                #pragma unroll
                for (int j = 0; j < 8; j++)
                    acc[i][j] += a[i] * b[j];
        }
        __syncthreads();
    }

    // Epilogue
    const int c0 = n0 / CHUNK;
    float qnr[8];
    int mls[8];
    #pragma unroll
    for (int i = 0; i < 8; i++) {
        mls[i] = (i < 4) ? (ty * 4 + i) : (64 + ty * 4 + i - 4);
        qnr[i] = qn[m0 + mls[i]];
    }
    float cacc0[8] = {}, cacc1[8] = {};

    #pragma unroll
    for (int j = 0; j < 8; j++) {
        const int nl = (j < 4) ? (tx * 4 + j) : (64 + tx * 4 + j - 4);
        const int gn = n0 + nl;
        if (gn < N) {
            const float cnr = cn[gn];
            const int cls = cy[gn];
            const bool hi = (gn / CHUNK) != c0;
            #pragma unroll
            for (int i = 0; i < 8; i++) {
                float s = qnr[i] + cnr - 2.f * acc[i][j];
                float ed = __expf(-sqrtf(fmaxf(s, 0.f)));
                atomicAdd(&lg[mls[i]][cls], ed);
                float ee = __expf(ed);
                if (hi) cacc1[i] += ee; else cacc0[i] += ee;
            }
        }
    }
    #pragma unroll
    for (int i = 0; i < 8; i++) {
        if (cacc0[i] != 0.f) atomicAdd(&ch[mls[i]][0], cacc0[i]);
        if (cacc1[i] != 0.f) atomicAdd(&ch[mls[i]][1], cacc1[i]);
    }
    __syncthreads();

    // Flush to global
    for (int idx = tid; idx < TS * D_OUT; idx += 256) {
        const int ml = idx / D_OUT, k = idx % D_OUT;
        const float v = lg[ml][k];
        if (v != 0.f) atomicAdd(&logits[(size_t)(m0 + ml) * D_OUT + k], v);
    }
    for (int idx = tid; idx < TS * 2; idx += 256) {
        const int ml = idx >> 1, cc = idx & 1;
        const int gc = c0 + cc;
        const float v = ch[ml][cc];
        if (gc < NCHUNK && v != 0.f)
            atomicAdd(&chunks[(size_t)(m0 + ml) * NCHUNK + gc], v);
    }
}

// ---------------------------------------------------------------------------
// Finalize: out[b][k] = log(logits[b][k]) - sum_c log(chunks[b][c])
// ---------------------------------------------------------------------------
__global__ void k_finalize(const float* __restrict__ logits,
                           const float* __restrict__ chunks,
                           float* __restrict__ out)
{
    const int b = blockIdx.x * blockDim.x + threadIdx.x;
    if (b >= B_Q) return;
    float lse = 0.f;
    #pragma unroll
    for (int c = 0; c < NCHUNK; c++) lse += logf(chunks[b * NCHUNK + c]);
    #pragma unroll
    for (int k = 0; k < D_OUT; k++)
        out[b * D_OUT + k] = logf(logits[b * D_OUT + k]) - lse;
}

// ---------------------------------------------------------------------------
// Launch
// ---------------------------------------------------------------------------
extern "C" void kernel_launch(void* const* d_in, const int* in_sizes, int n_in,
                              void* d_out, int out_size)
{
    const float* x_num = (const float*)d_in[0];
    const float* x_cat = (const float*)d_in[1];
    const float* c_num = (const float*)d_in[2];
    const float* c_cat = (const float*)d_in[3];
    const int*   c_y   = (const int*)d_in[4];
    const float* W1    = (const float*)d_in[5];
    const float* b1    = (const float*)d_in[6];
    const float* W2    = (const float*)d_in[7];
    const float* b2    = (const float*)d_in[8];
    float* out = (float*)d_out;

    float *pH, *pC, *pQH, *pQ, *pcn, *pqn, *plog, *pch;
    cudaGetSymbolAddress((void**)&pH,  g_H);
    cudaGetSymbolAddress((void**)&pC,  g_C);
    cudaGetSymbolAddress((void**)&pQH, g_QH);
    cudaGetSymbolAddress((void**)&pQ,  g_Q);
    cudaGetSymbolAddress((void**)&pcn, g_cnorm);
    cudaGetSymbolAddress((void**)&pqn, g_qnorm);
    cudaGetSymbolAddress((void**)&plog, g_logits);
    cudaGetSymbolAddress((void**)&pch, g_chunks);

    const int nblk = (N_CAND + TS - 1) / TS;   // 782

    k_zero<<<(B_Q * NCHUNK + 255) / 256, 256>>>();

    // Candidate encode
    k_gemm_enc<true,  true ><<<dim3(DIM / TS, nblk), 256>>>(c_num, c_cat, W1, b1, pH, N_CAND, D_IN);
    k_gemm_enc<false, false><<<dim3(DIM / TS, nblk), 256>>>(pH, nullptr, W2, b2, pC, N_CAND, DIM);
    // Query encode
    k_gemm_enc<true,  true ><<<dim3(DIM / TS, B_Q / TS), 256>>>(x_num, x_cat, W1, b1, pQH, B_Q, D_IN);
    k_gemm_enc<false, false><<<dim3(DIM / TS, B_Q / TS), 256>>>(pQH, nullptr, W2, b2, pQ, B_Q, DIM);

    k_norm<<<(N_CAND + 7) / 8, 256>>>(pC, pcn, N_CAND);
    k_norm<<<B_Q / 8, 256>>>(pQ, pqn, B_Q);

    k_dist<<<dim3(nblk, B_Q / TS), 256>>>(pQ, pC, pqn, pcn, c_y, plog, pch, N_CAND);

    k_finalize<<<(B_Q + 255) / 256, 256>>>(plog, pch, out);
}